// round 11
// baseline (speedup 1.0000x reference)
#include <cuda_runtime.h>
#include <cuda_fp16.h>
#include <math_constants.h>
#include <cstdint>

#define Bn 4
#define Tn 1024
#define Cn 1024
#define Hn 16
#define Dn 64

// fp16 scratch (device globals; no cudaMalloc anywhere)
__device__ __half g_hx[Bn * Tn * Cn];                  // x fp16 [4096][1024]
__device__ __half g_hw[3 * Hn * Dn * Cn];              // W^T fp16 [proj*16+h][n=64][k=1024]
__device__ __half g_hwpt[Cn * Cn];                     // Wp^T fp16 [n=1024][k=1024]
__device__ __half g_qh[Bn * Hn * Tn * Dn];
__device__ __half g_kh[Bn * Hn * Tn * Dn];
__device__ __half g_vh[Bn * Hn * Tn * Dn];
__device__ __half g_atth[Bn * Tn * Hn * Dn];           // [b][t][h*64+d] fp16

// ---------------------------------------------------------------------------
// mma / ldmatrix / cp.async helpers
// ---------------------------------------------------------------------------
__device__ __forceinline__ void mma_f16(float c[4],
                                        uint32_t a0, uint32_t a1, uint32_t a2, uint32_t a3,
                                        uint32_t b0, uint32_t b1)
{
    asm volatile(
        "mma.sync.aligned.m16n8k16.row.col.f32.f16.f16.f32 "
        "{%0,%1,%2,%3}, {%4,%5,%6,%7}, {%8,%9}, {%0,%1,%2,%3};"
        : "+f"(c[0]), "+f"(c[1]), "+f"(c[2]), "+f"(c[3])
        : "r"(a0), "r"(a1), "r"(a2), "r"(a3), "r"(b0), "r"(b1));
}

__device__ __forceinline__ uint32_t smaddr(const void* p) {
    return (uint32_t)__cvta_generic_to_shared(p);
}

__device__ __forceinline__ void ldsm_x4(uint32_t& r0, uint32_t& r1,
                                        uint32_t& r2, uint32_t& r3, uint32_t addr)
{
    asm volatile("ldmatrix.sync.aligned.m8n8.x4.shared.b16 {%0,%1,%2,%3}, [%4];"
                 : "=r"(r0), "=r"(r1), "=r"(r2), "=r"(r3) : "r"(addr));
}

__device__ __forceinline__ void ldsm_x4_trans(uint32_t& r0, uint32_t& r1,
                                              uint32_t& r2, uint32_t& r3, uint32_t addr)
{
    asm volatile("ldmatrix.sync.aligned.m8n8.x4.trans.shared.b16 {%0,%1,%2,%3}, [%4];"
                 : "=r"(r0), "=r"(r1), "=r"(r2), "=r"(r3) : "r"(addr));
}

__device__ __forceinline__ uint32_t packh2(float lo, float hi) {
    __half2 h = __floats2half2_rn(lo, hi);
    return *(uint32_t*)&h;
}

__device__ __forceinline__ void cp16(uint32_t dst, const void* src) {
    asm volatile("cp.async.cg.shared.global [%0], [%1], 16;" :: "r"(dst), "l"(src));
}
__device__ __forceinline__ void cp_commit() {
    asm volatile("cp.async.commit_group;");
}
__device__ __forceinline__ void cp_wait0() {
    asm volatile("cp.async.wait_group 0;");
}
__device__ __forceinline__ void cp_wait1() {
    asm volatile("cp.async.wait_group 1;");
}

// ---------------------------------------------------------------------------
// Pre-pass: convert x -> fp16
// ---------------------------------------------------------------------------
__global__ __launch_bounds__(256) void conv_x_kernel(const float* __restrict__ src)
{
    int i = (blockIdx.x * 256 + threadIdx.x) * 4;
    float4 v = *(const float4*)&src[i];
    __half2 h0 = __floats2half2_rn(v.x, v.y);
    __half2 h1 = __floats2half2_rn(v.z, v.w);
    uint2 pk = make_uint2(*(uint32_t*)&h0, *(uint32_t*)&h1);
    *(uint2*)&g_hx[i] = pk;
}

// ---------------------------------------------------------------------------
// Pre-pass: transpose + convert Wq/Wk/Wv -> g_hw [48][64][1024]
// ---------------------------------------------------------------------------
__global__ __launch_bounds__(256) void transcvt_w3(
    const float* __restrict__ Wq, const float* __restrict__ Wk,
    const float* __restrict__ Wv)
{
    __shared__ float tile[32][33];
    const int tid = threadIdx.x;
    const int m = blockIdx.z;
    const float* src = (m < 16 ? Wq : (m < 32 ? Wk : Wv)) + (size_t)(m & 15) * Cn * Dn;
    __half* dst = g_hw + (size_t)m * Dn * Cn;
    const int r0 = blockIdx.y * 32;
    const int c0 = blockIdx.x * 32;

    {
        int rr = tid >> 3;
        int cc = (tid & 7) * 4;
        float4 v = *(const float4*)&src[(size_t)(r0 + rr) * Dn + c0 + cc];
        tile[rr][cc + 0] = v.x;
        tile[rr][cc + 1] = v.y;
        tile[rr][cc + 2] = v.z;
        tile[rr][cc + 3] = v.w;
    }
    __syncthreads();
    {
        int cw = tid >> 3;
        int rw = (tid & 7) * 4;
        __half2 h0 = __floats2half2_rn(tile[rw + 0][cw], tile[rw + 1][cw]);
        __half2 h1 = __floats2half2_rn(tile[rw + 2][cw], tile[rw + 3][cw]);
        uint2 pk = make_uint2(*(uint32_t*)&h0, *(uint32_t*)&h1);
        *(uint2*)&dst[(size_t)(c0 + cw) * Cn + r0 + rw] = pk;
    }
}

// ---------------------------------------------------------------------------
// Pre-pass: transpose + convert Wp -> g_hwpt [n][k]
// ---------------------------------------------------------------------------
__global__ __launch_bounds__(256) void transcvt_kernel(
    const float* __restrict__ src, __half* __restrict__ dst, int R, int C)
{
    __shared__ float tile[32][33];
    const int tid = threadIdx.x;
    const int r0 = blockIdx.y * 32;
    const int c0 = blockIdx.x * 32;

    {
        int rr = tid >> 3;
        int cc = (tid & 7) * 4;
        float4 v = *(const float4*)&src[(size_t)(r0 + rr) * C + c0 + cc];
        tile[rr][cc + 0] = v.x;
        tile[rr][cc + 1] = v.y;
        tile[rr][cc + 2] = v.z;
        tile[rr][cc + 3] = v.w;
    }
    __syncthreads();
    {
        int cw = tid >> 3;
        int rw = (tid & 7) * 4;
        __half2 h0 = __floats2half2_rn(tile[rw + 0][cw], tile[rw + 1][cw]);
        __half2 h1 = __floats2half2_rn(tile[rw + 2][cw], tile[rw + 3][cw]);
        uint2 pk = make_uint2(*(uint32_t*)&h0, *(uint32_t*)&h1);
        *(uint2*)&dst[(size_t)(c0 + cw) * R + r0 + rw] = pk;
    }
}

// ---------------------------------------------------------------------------
// Kernel 1: fused QKV projection, fp16 mma + ldmatrix + cp.async 3-stage.
// Block tile 128x128 (2 heads), Kc=64. Grid (24, 32): x=py, y=rowBase.
// ---------------------------------------------------------------------------
#define GEMM_STAGE_HALFS (256 * 72)              // As 128*72 + Bs 128*72
#define GEMM_SMEM_BYTES (3 * GEMM_STAGE_HALFS * 2)   // 110592 B

__global__ __launch_bounds__(256, 2) void qkv_fp16()
{
    extern __shared__ __align__(16) __half sm[];

    const int tid = threadIdx.x;
    const int lane = tid & 31;
    const int warp = tid >> 5;
    const int g = lane >> 2;
    const int tg = lane & 3;
    const int wmBase = (warp & 3) * 32;
    const int wnBase = (warp >> 2) * 64;

    const int py = blockIdx.x;                   // 0..23
    const int rowBase = blockIdx.y * 128;
    const int proj = py >> 3;
    const int hp = py & 7;

    const __half* A = g_hx + (size_t)rowBase * Cn;
    const __half* B = g_hw + (size_t)(proj * Hn + hp * 2) * Dn * Cn;

    __half* outbase = (proj == 0 ? g_qh : (proj == 1 ? g_kh : g_vh));
    const int b  = rowBase >> 10;
    const int t0 = rowBase & (Tn - 1);

    const int ar = tid >> 1;
    const int ah = (tid & 1) * 32;
    const int r16 = lane & 15;
    const int ch = (lane >> 4) * 8;

    auto stage_load = [&](int s, int k0) {
        __half* As = sm + s * GEMM_STAGE_HALFS;
        __half* Bs = As + 128 * 72;
#pragma unroll
        for (int i = 0; i < 4; i++) {
            cp16(smaddr(&As[ar * 72 + ah + i * 8]), &A[(size_t)ar * Cn + k0 + ah + i * 8]);
            cp16(smaddr(&Bs[ar * 72 + ah + i * 8]), &B[(size_t)ar * Cn + k0 + ah + i * 8]);
        }
        cp_commit();
    };

    float acc[2][8][4];
#pragma unroll
    for (int mt = 0; mt < 2; mt++)
#pragma unroll
        for (int j = 0; j < 8; j++)
#pragma unroll
            for (int e = 0; e < 4; e++) acc[mt][j][e] = 0.f;

    stage_load(0, 0);
    stage_load(1, 64);

    for (int i = 0; i < 16; i++) {
        const int cur = i % 3;
        if (i == 15) cp_wait0(); else cp_wait1();
        __syncthreads();
        if (i + 2 < 16) stage_load((i + 2) % 3, (i + 2) * 64);

        const __half* As = sm + cur * GEMM_STAGE_HALFS;
        const __half* Bs = As + 128 * 72;

#pragma unroll
        for (int kk = 0; kk < 4; kk++) {
            const int kb = kk * 16;
            uint32_t af[2][4], bf0[8], bf1[8];
#pragma unroll
            for (int mt = 0; mt < 2; mt++)
                ldsm_x4(af[mt][0], af[mt][1], af[mt][2], af[mt][3],
                        smaddr(&As[(wmBase + mt * 16 + r16) * 72 + kb + ch]));
            ldsm_x4(bf0[0], bf0[1], bf0[2], bf0[3],
                    smaddr(&Bs[(wnBase + lane) * 72 + kb]));
            ldsm_x4(bf0[4], bf0[5], bf0[6], bf0[7],
                    smaddr(&Bs[(wnBase + 32 + lane) * 72 + kb]));
            ldsm_x4(bf1[0], bf1[1], bf1[2], bf1[3],
                    smaddr(&Bs[(wnBase + lane) * 72 + kb + 8]));
            ldsm_x4(bf1[4], bf1[5], bf1[6], bf1[7],
                    smaddr(&Bs[(wnBase + 32 + lane) * 72 + kb + 8]));
#pragma unroll
            for (int mt = 0; mt < 2; mt++)
#pragma unroll
                for (int j = 0; j < 8; j++)
                    mma_f16(acc[mt][j], af[mt][0], af[mt][1], af[mt][2], af[mt][3],
                            bf0[j], bf1[j]);
        }
    }

#pragma unroll
    for (int mt = 0; mt < 2; mt++) {
        int row0 = wmBase + mt * 16 + g;
#pragma unroll
        for (int j = 0; j < 8; j++) {
            int col = wnBase + j * 8 + tg * 2;
            int h = hp * 2 + (col >> 6);
            int d = col & 63;
            __half* ob = outbase + ((size_t)(b * Hn + h) * Tn + t0) * Dn + d;
            *(__half2*)&ob[(size_t)row0 * Dn] =
                __floats2half2_rn(acc[mt][j][0], acc[mt][j][1]);
            *(__half2*)&ob[(size_t)(row0 + 8) * Dn] =
                __floats2half2_rn(acc[mt][j][2], acc[mt][j][3]);
        }
    }
}

// ---------------------------------------------------------------------------
// Kernel 2: causal flash attention, fp16 mma + ldmatrix + cp.async 3-stage K/V.
// ---------------------------------------------------------------------------
#define ATTN_KV_STAGE_HALFS (128 * 72)   // Ks 64*72 + Vs 64*72
#define ATTN_SMEM_HALFS (128 * 72 + 3 * ATTN_KV_STAGE_HALFS)

__global__ __launch_bounds__(256) void attn_fp16()
{
    extern __shared__ __align__(16) __half smh[];
    __half* Qs = smh;                        // [128][72] staging only
    __half* KV = smh + 128 * 72;             // 3 stages of (Ks,Vs)

    const int tid = threadIdx.x;
    const int lane = tid & 31;
    const int warp = tid >> 5;
    const int g = lane >> 2;
    const int tg = lane & 3;
    const int wm = warp * 16;
    const int qt = (int)gridDim.x - 1 - (int)blockIdx.x;
    const int bh = blockIdx.y;

    const int r16 = lane & 15;
    const int ch = (lane >> 4) * 8;

    uint32_t qf[4][4];
    {
        const __half* qb = g_qh + ((size_t)bh * Tn + (size_t)qt * 128) * Dn;
        int r = tid >> 1;
        int hs = (tid & 1) * 32;
#pragma unroll
        for (int i = 0; i < 4; i++)
            *(uint4*)&Qs[r * 72 + hs + i * 8] =
                *(const uint4*)&qb[(size_t)r * Dn + hs + i * 8];
        __syncwarp();
#pragma unroll
        for (int kk = 0; kk < 4; kk++)
            ldsm_x4(qf[kk][0], qf[kk][1], qf[kk][2], qf[kk][3],
                    smaddr(&Qs[(wm + r16) * 72 + kk * 16 + ch]));
    }

    float m0 = -CUDART_INF_F, m1 = -CUDART_INF_F;
    float l0 = 0.f, l1 = 0.f;
    float oacc[8][4];
#pragma unroll
    for (int j = 0; j < 8; j++)
#pragma unroll
        for (int e = 0; e < 4; e++) oacc[j][e] = 0.f;

    const int row0 = qt * 128 + wm + g;
    const int row1 = row0 + 8;
    const int rowWarpMax = qt * 128 + wm + 15;

    const __half* kbase = g_kh + (size_t)bh * Tn * Dn;
    const __half* vbase = g_vh + (size_t)bh * Tn * Dn;
    const int sr = tid >> 2;
    const int sh = (tid & 3) * 16;

    auto kv_load = [&](int s, int st) {
        __half* Ks = KV + s * ATTN_KV_STAGE_HALFS;
        __half* Vs = Ks + 64 * 72;
        const __half* kn = kbase + (size_t)st * 64 * Dn;
        const __half* vn = vbase + (size_t)st * 64 * Dn;
#pragma unroll
        for (int i = 0; i < 2; i++) {
            cp16(smaddr(&Ks[sr * 72 + sh + i * 8]), &kn[(size_t)sr * Dn + sh + i * 8]);
            cp16(smaddr(&Vs[sr * 72 + sh + i * 8]), &vn[(size_t)sr * Dn + sh + i * 8]);
        }
        cp_commit();
    };

    const int nst = 2 * qt + 2;
    kv_load(0, 0);
    if (nst > 1) kv_load(1, 1);

    for (int st = 0; st < nst; st++) {
        if (st == nst - 1) cp_wait0(); else cp_wait1();
        __syncthreads();
        if (st + 2 < nst) kv_load((st + 2) % 3, st + 2);

        if (st * 64 <= rowWarpMax) {
            const __half* Ks = KV + (st % 3) * ATTN_KV_STAGE_HALFS;
            const __half* Vs = Ks + 64 * 72;

            float c[8][4];
#pragma unroll
            for (int j = 0; j < 8; j++)
#pragma unroll
                for (int e = 0; e < 4; e++) c[j][e] = 0.f;

#pragma unroll
            for (int kk = 0; kk < 4; kk++) {
                const int kb = kk * 16;
                uint32_t b0lo[4], b0hi[4], b1lo[4], b1hi[4];
                ldsm_x4(b0lo[0], b0lo[1], b0lo[2], b0lo[3],
                        smaddr(&Ks[lane * 72 + kb]));
                ldsm_x4(b0hi[0], b0hi[1], b0hi[2], b0hi[3],
                        smaddr(&Ks[(32 + lane) * 72 + kb]));
                ldsm_x4(b1lo[0], b1lo[1], b1lo[2], b1lo[3],
                        smaddr(&Ks[lane * 72 + kb + 8]));
                ldsm_x4(b1hi[0], b1hi[1], b1hi[2], b1hi[3],
                        smaddr(&Ks[(32 + lane) * 72 + kb + 8]));
#pragma unroll
                for (int j = 0; j < 4; j++) {
                    mma_f16(c[j], qf[kk][0], qf[kk][1], qf[kk][2], qf[kk][3],
                            b0lo[j], b1lo[j]);
                    mma_f16(c[j + 4], qf[kk][0], qf[kk][1], qf[kk][2], qf[kk][3],
                            b0hi[j], b1hi[j]);
                }
            }

            const float scale = 0.125f;
            const bool maskt = (st * 64 + 63 > qt * 128);
#pragma unroll
            for (int j = 0; j < 8; j++) {
                int col = st * 64 + j * 8 + tg * 2;
                if (maskt) {
                    c[j][0] = (col     > row0) ? -CUDART_INF_F : c[j][0] * scale;
                    c[j][1] = (col + 1 > row0) ? -CUDART_INF_F : c[j][1] * scale;
                    c[j][2] = (col     > row1) ? -CUDART_INF_F : c[j][2] * scale;
                    c[j][3] = (col + 1 > row1) ? -CUDART_INF_F : c[j][3] * scale;
                } else {
                    c[j][0] *= scale; c[j][1] *= scale;
                    c[j][2] *= scale; c[j][3] *= scale;
                }
            }

            float t0 = -CUDART_INF_F, t1 = -CUDART_INF_F;
#pragma unroll
            for (int j = 0; j < 8; j++) {
                t0 = fmaxf(t0, fmaxf(c[j][0], c[j][1]));
                t1 = fmaxf(t1, fmaxf(c[j][2], c[j][3]));
            }
            t0 = fmaxf(t0, __shfl_xor_sync(0xffffffffu, t0, 1));
            t0 = fmaxf(t0, __shfl_xor_sync(0xffffffffu, t0, 2));
            t1 = fmaxf(t1, __shfl_xor_sync(0xffffffffu, t1, 1));
            t1 = fmaxf(t1, __shfl_xor_sync(0xffffffffu, t1, 2));

            float nm0 = fmaxf(m0, t0), nm1 = fmaxf(m1, t1);
            float al0 = __expf(m0 - nm0), al1 = __expf(m1 - nm1);
            float s0 = 0.f, s1 = 0.f;
#pragma unroll
            for (int j = 0; j < 8; j++) {
                c[j][0] = __expf(c[j][0] - nm0);
                c[j][1] = __expf(c[j][1] - nm0);
                c[j][2] = __expf(c[j][2] - nm1);
                c[j][3] = __expf(c[j][3] - nm1);
                s0 += c[j][0] + c[j][1];
                s1 += c[j][2] + c[j][3];
            }
            s0 += __shfl_xor_sync(0xffffffffu, s0, 1);
            s0 += __shfl_xor_sync(0xffffffffu, s0, 2);
            s1 += __shfl_xor_sync(0xffffffffu, s1, 1);
            s1 += __shfl_xor_sync(0xffffffffu, s1, 2);

            l0 = l0 * al0 + s0;  m0 = nm0;
            l1 = l1 * al1 + s1;  m1 = nm1;

#pragma unroll
            for (int j = 0; j < 8; j++) {
                oacc[j][0] *= al0; oacc[j][1] *= al0;
                oacc[j][2] *= al1; oacc[j][3] *= al1;
            }

#pragma unroll
            for (int kk = 0; kk < 4; kk++) {
                const int kb = kk * 16;
                uint32_t a0 = packh2(c[2 * kk][0], c[2 * kk][1]);
                uint32_t a1 = packh2(c[2 * kk][2], c[2 * kk][3]);
                uint32_t a2 = packh2(c[2 * kk + 1][0], c[2 * kk + 1][1]);
                uint32_t a3 = packh2(c[2 * kk + 1][2], c[2 * kk + 1][3]);

                uint32_t v0lo[4], v0hi[4], v1lo[4], v1hi[4];
                const int srow = lane & 7;
                const int dcol = (lane >> 3) * 8;
                ldsm_x4_trans(v0lo[0], v0lo[1], v0lo[2], v0lo[3],
                              smaddr(&Vs[(kb + srow) * 72 + dcol]));
                ldsm_x4_trans(v0hi[0], v0hi[1], v0hi[2], v0hi[3],
                              smaddr(&Vs[(kb + srow) * 72 + dcol + 32]));
                ldsm_x4_trans(v1lo[0], v1lo[1], v1lo[2], v1lo[3],
                              smaddr(&Vs[(kb + 8 + srow) * 72 + dcol]));
                ldsm_x4_trans(v1hi[0], v1hi[1], v1hi[2], v1hi[3],
                              smaddr(&Vs[(kb + 8 + srow) * 72 + dcol + 32]));
#pragma unroll
                for (int j = 0; j < 4; j++) {
                    mma_f16(oacc[j], a0, a1, a2, a3, v0lo[j], v1lo[j]);
                    mma_f16(oacc[j + 4], a0, a1, a2, a3, v0hi[j], v1hi[j]);
                }
            }
        }
    }

    const int b = bh >> 4, h = bh & 15;
    __half* ob = g_atth + ((size_t)b * Tn + (size_t)qt * 128) * (Hn * Dn) + h * Dn;
    float inv0 = 1.f / l0, inv1 = 1.f / l1;
#pragma unroll
    for (int j = 0; j < 8; j++) {
        int col = j * 8 + tg * 2;
        *(__half2*)&ob[(size_t)(wm + g) * (Hn * Dn) + col] =
            __floats2half2_rn(oacc[j][0] * inv0, oacc[j][1] * inv0);
        *(__half2*)&ob[(size_t)(wm + g + 8) * (Hn * Dn) + col] =
            __floats2half2_rn(oacc[j][2] * inv1, oacc[j][3] * inv1);
    }
}

// ---------------------------------------------------------------------------
// Kernel 3: output projection, fp16 mma + ldmatrix + cp.async 3-stage.
// Block tile 128x128. Grid (8, 32): x=n0, y=rowBase.
// ---------------------------------------------------------------------------
__global__ __launch_bounds__(256, 2) void proj_fp16(
    const float* __restrict__ bp, float* __restrict__ out)
{
    extern __shared__ __align__(16) __half sm[];

    const int tid = threadIdx.x;
    const int lane = tid & 31;
    const int warp = tid >> 5;
    const int g = lane >> 2;
    const int tg = lane & 3;
    const int wmBase = (warp & 3) * 32;
    const int wnBase = (warp >> 2) * 64;

    const int n0 = blockIdx.x * 128;
    const int rowBase = blockIdx.y * 128;

    const __half* A = g_atth + (size_t)rowBase * Cn;
    const __half* B = g_hwpt + (size_t)n0 * Cn;
    float* O = out + (size_t)rowBase * Cn + n0;

    const int ar = tid >> 1;
    const int ah = (tid & 1) * 32;
    const int r16 = lane & 15;
    const int ch = (lane >> 4) * 8;

    auto stage_load = [&](int s, int k0) {
        __half* As = sm + s * GEMM_STAGE_HALFS;
        __half* Bs = As + 128 * 72;
#pragma unroll
        for (int i = 0; i < 4; i++) {
            cp16(smaddr(&As[ar * 72 + ah + i * 8]), &A[(size_t)ar * Cn + k0 + ah + i * 8]);
            cp16(smaddr(&Bs[ar * 72 + ah + i * 8]), &B[(size_t)ar * Cn + k0 + ah + i * 8]);
        }
        cp_commit();
    };

    float acc[2][8][4];
#pragma unroll
    for (int mt = 0; mt < 2; mt++)
#pragma unroll
        for (int j = 0; j < 8; j++)
#pragma unroll
            for (int e = 0; e < 4; e++) acc[mt][j][e] = 0.f;

    stage_load(0, 0);
    stage_load(1, 64);

    for (int i = 0; i < 16; i++) {
        const int cur = i % 3;
        if (i == 15) cp_wait0(); else cp_wait1();
        __syncthreads();
        if (i + 2 < 16) stage_load((i + 2) % 3, (i + 2) * 64);

        const __half* As = sm + cur * GEMM_STAGE_HALFS;
        const __half* Bs = As + 128 * 72;

#pragma unroll
        for (int kk = 0; kk < 4; kk++) {
            const int kb = kk * 16;
            uint32_t af[2][4], bf0[8], bf1[8];
#pragma unroll
            for (int mt = 0; mt < 2; mt++)
                ldsm_x4(af[mt][0], af[mt][1], af[mt][2], af[mt][3],
                        smaddr(&As[(wmBase + mt * 16 + r16) * 72 + kb + ch]));
            ldsm_x4(bf0[0], bf0[1], bf0[2], bf0[3],
                    smaddr(&Bs[(wnBase + lane) * 72 + kb]));
            ldsm_x4(bf0[4], bf0[5], bf0[6], bf0[7],
                    smaddr(&Bs[(wnBase + 32 + lane) * 72 + kb]));
            ldsm_x4(bf1[0], bf1[1], bf1[2], bf1[3],
                    smaddr(&Bs[(wnBase + lane) * 72 + kb + 8]));
            ldsm_x4(bf1[4], bf1[5], bf1[6], bf1[7],
                    smaddr(&Bs[(wnBase + 32 + lane) * 72 + kb + 8]));
#pragma unroll
            for (int mt = 0; mt < 2; mt++)
#pragma unroll
                for (int j = 0; j < 8; j++)
                    mma_f16(acc[mt][j], af[mt][0], af[mt][1], af[mt][2], af[mt][3],
                            bf0[j], bf1[j]);
        }
    }

#pragma unroll
    for (int mt = 0; mt < 2; mt++) {
        int row0 = wmBase + mt * 16 + g;
#pragma unroll
        for (int j = 0; j < 8; j++) {
            int col = wnBase + j * 8 + tg * 2;
            float b0 = bp[n0 + col];
            float b1 = bp[n0 + col + 1];
            *(float2*)&O[(size_t)row0 * Cn + col] =
                make_float2(acc[mt][j][0] + b0, acc[mt][j][1] + b1);
            *(float2*)&O[(size_t)(row0 + 8) * Cn + col] =
                make_float2(acc[mt][j][2] + b0, acc[mt][j][3] + b1);
        }
    }
}

// ---------------------------------------------------------------------------

extern "C" void kernel_launch(void* const* d_in, const int* in_sizes, int n_in,
                              void* d_out, int out_size)
{
    (void)in_sizes; (void)n_in; (void)out_size;
    const float* x  = (const float*)d_in[0];
    const float* Wq = (const float*)d_in[1];
    const float* Wk = (const float*)d_in[2];
    const float* Wv = (const float*)d_in[3];
    const float* Wp = (const float*)d_in[4];
    const float* bp = (const float*)d_in[5];
    float* out = (float*)d_out;

    __half* hwpt = nullptr;
    cudaGetSymbolAddress((void**)&hwpt, g_hwpt);

    const size_t attn_smem = ATTN_SMEM_HALFS * sizeof(__half);   // 73728 B
    cudaFuncSetAttribute(attn_fp16,
                         cudaFuncAttributeMaxDynamicSharedMemorySize,
                         (int)attn_smem);
    cudaFuncSetAttribute(qkv_fp16,
                         cudaFuncAttributeMaxDynamicSharedMemorySize,
                         GEMM_SMEM_BYTES);                        // 110592 B
    cudaFuncSetAttribute(proj_fp16,
                         cudaFuncAttributeMaxDynamicSharedMemorySize,
                         GEMM_SMEM_BYTES);

    conv_x_kernel<<<Bn * Tn * Cn / (256 * 4), 256>>>(x);
    transcvt_w3<<<dim3(2, 32, 48), 256>>>(Wq, Wk, Wv);
    transcvt_kernel<<<dim3(32, 32, 1), 256>>>(Wp, hwpt, Cn, Cn);

    qkv_fp16<<<dim3(24, 32), 256, GEMM_SMEM_BYTES>>>();
    attn_fp16<<<dim3(Tn / 128, Bn * Hn), 256, attn_smem>>>();
    proj_fp16<<<dim3(8, 32), 256, GEMM_SMEM_BYTES>>>(bp, out);
}

// round 13
// speedup vs baseline: 1.0472x; 1.0472x over previous
#include <cuda_runtime.h>
#include <cuda_fp16.h>
#include <math_constants.h>
#include <cstdint>

#define Bn 4
#define Tn 1024
#define Cn 1024
#define Hn 16
#define Dn 64

// fp16 scratch (device globals; no cudaMalloc anywhere)
__device__ __half g_hx[Bn * Tn * Cn];                  // x fp16 [4096][1024]
__device__ __half g_hw[3 * Hn * Dn * Cn];              // W^T fp16 [proj*16+h][n=64][k=1024]
__device__ __half g_hwpt[Cn * Cn];                     // Wp^T fp16 [n=1024][k=1024]
__device__ __half g_qh[Bn * Hn * Tn * Dn];
__device__ __half g_kh[Bn * Hn * Tn * Dn];
__device__ __half g_vh[Bn * Hn * Tn * Dn];
__device__ __half g_atth[Bn * Tn * Hn * Dn];           // [b][t][h*64+d] fp16

// ---------------------------------------------------------------------------
// mma / ldmatrix / cp.async helpers
// ---------------------------------------------------------------------------
__device__ __forceinline__ void mma_f16(float c[4],
                                        uint32_t a0, uint32_t a1, uint32_t a2, uint32_t a3,
                                        uint32_t b0, uint32_t b1)
{
    asm volatile(
        "mma.sync.aligned.m16n8k16.row.col.f32.f16.f16.f32 "
        "{%0,%1,%2,%3}, {%4,%5,%6,%7}, {%8,%9}, {%0,%1,%2,%3};"
        : "+f"(c[0]), "+f"(c[1]), "+f"(c[2]), "+f"(c[3])
        : "r"(a0), "r"(a1), "r"(a2), "r"(a3), "r"(b0), "r"(b1));
}

__device__ __forceinline__ uint32_t smaddr(const void* p) {
    return (uint32_t)__cvta_generic_to_shared(p);
}

__device__ __forceinline__ void ldsm_x4(uint32_t& r0, uint32_t& r1,
                                        uint32_t& r2, uint32_t& r3, uint32_t addr)
{
    asm volatile("ldmatrix.sync.aligned.m8n8.x4.shared.b16 {%0,%1,%2,%3}, [%4];"
                 : "=r"(r0), "=r"(r1), "=r"(r2), "=r"(r3) : "r"(addr));
}

__device__ __forceinline__ void ldsm_x4_trans(uint32_t& r0, uint32_t& r1,
                                              uint32_t& r2, uint32_t& r3, uint32_t addr)
{
    asm volatile("ldmatrix.sync.aligned.m8n8.x4.trans.shared.b16 {%0,%1,%2,%3}, [%4];"
                 : "=r"(r0), "=r"(r1), "=r"(r2), "=r"(r3) : "r"(addr));
}

__device__ __forceinline__ uint32_t packh2(float lo, float hi) {
    __half2 h = __floats2half2_rn(lo, hi);
    return *(uint32_t*)&h;
}

__device__ __forceinline__ void cp16(uint32_t dst, const void* src) {
    asm volatile("cp.async.cg.shared.global [%0], [%1], 16;" :: "r"(dst), "l"(src));
}
__device__ __forceinline__ void cp_commit() {
    asm volatile("cp.async.commit_group;");
}
__device__ __forceinline__ void cp_wait0() {
    asm volatile("cp.async.wait_group 0;");
}
__device__ __forceinline__ void cp_wait1() {
    asm volatile("cp.async.wait_group 1;");
}

// ---------------------------------------------------------------------------
// Pre-pass: convert x -> fp16
// ---------------------------------------------------------------------------
__global__ __launch_bounds__(256) void conv_x_kernel(const float* __restrict__ src)
{
    int i = (blockIdx.x * 256 + threadIdx.x) * 4;
    float4 v = *(const float4*)&src[i];
    __half2 h0 = __floats2half2_rn(v.x, v.y);
    __half2 h1 = __floats2half2_rn(v.z, v.w);
    uint2 pk = make_uint2(*(uint32_t*)&h0, *(uint32_t*)&h1);
    *(uint2*)&g_hx[i] = pk;
}

// ---------------------------------------------------------------------------
// Pre-pass: transpose + convert Wq/Wk/Wv -> g_hw [48][64][1024]
// ---------------------------------------------------------------------------
__global__ __launch_bounds__(256) void transcvt_w3(
    const float* __restrict__ Wq, const float* __restrict__ Wk,
    const float* __restrict__ Wv)
{
    __shared__ float tile[32][33];
    const int tid = threadIdx.x;
    const int m = blockIdx.z;
    const float* src = (m < 16 ? Wq : (m < 32 ? Wk : Wv)) + (size_t)(m & 15) * Cn * Dn;
    __half* dst = g_hw + (size_t)m * Dn * Cn;
    const int r0 = blockIdx.y * 32;
    const int c0 = blockIdx.x * 32;

    {
        int rr = tid >> 3;
        int cc = (tid & 7) * 4;
        float4 v = *(const float4*)&src[(size_t)(r0 + rr) * Dn + c0 + cc];
        tile[rr][cc + 0] = v.x;
        tile[rr][cc + 1] = v.y;
        tile[rr][cc + 2] = v.z;
        tile[rr][cc + 3] = v.w;
    }
    __syncthreads();
    {
        int cw = tid >> 3;
        int rw = (tid & 7) * 4;
        __half2 h0 = __floats2half2_rn(tile[rw + 0][cw], tile[rw + 1][cw]);
        __half2 h1 = __floats2half2_rn(tile[rw + 2][cw], tile[rw + 3][cw]);
        uint2 pk = make_uint2(*(uint32_t*)&h0, *(uint32_t*)&h1);
        *(uint2*)&dst[(size_t)(c0 + cw) * Cn + r0 + rw] = pk;
    }
}

// ---------------------------------------------------------------------------
// Pre-pass: transpose + convert Wp -> g_hwpt [n][k]
// ---------------------------------------------------------------------------
__global__ __launch_bounds__(256) void transcvt_kernel(
    const float* __restrict__ src, __half* __restrict__ dst, int R, int C)
{
    __shared__ float tile[32][33];
    const int tid = threadIdx.x;
    const int r0 = blockIdx.y * 32;
    const int c0 = blockIdx.x * 32;

    {
        int rr = tid >> 3;
        int cc = (tid & 7) * 4;
        float4 v = *(const float4*)&src[(size_t)(r0 + rr) * C + c0 + cc];
        tile[rr][cc + 0] = v.x;
        tile[rr][cc + 1] = v.y;
        tile[rr][cc + 2] = v.z;
        tile[rr][cc + 3] = v.w;
    }
    __syncthreads();
    {
        int cw = tid >> 3;
        int rw = (tid & 7) * 4;
        __half2 h0 = __floats2half2_rn(tile[rw + 0][cw], tile[rw + 1][cw]);
        __half2 h1 = __floats2half2_rn(tile[rw + 2][cw], tile[rw + 3][cw]);
        uint2 pk = make_uint2(*(uint32_t*)&h0, *(uint32_t*)&h1);
        *(uint2*)&dst[(size_t)(c0 + cw) * R + r0 + rw] = pk;
    }
}

// ---------------------------------------------------------------------------
// Kernel 1: fused QKV projection, fp16 mma + ldmatrix + cp.async 3-stage.
// Block tile 256x128 (2 heads), 512 threads (16 warps = 8m x 2n, warp 32x64).
// Kc=64. Grid (24, 16): x=py, y=rowBase/256.
// L2 traffic: A 192MB + B 96MB (B re-reads halved vs 128-row tile).
// ---------------------------------------------------------------------------
#define QKV_STAGE_HALFS (384 * 72)               // As 256*72 + Bs 128*72
#define QKV_SMEM_BYTES (3 * QKV_STAGE_HALFS * 2)     // 165888 B

__global__ __launch_bounds__(512, 1) void qkv_fp16()
{
    extern __shared__ __align__(16) __half sm[];

    const int tid = threadIdx.x;
    const int lane = tid & 31;
    const int warp = tid >> 5;
    const int g = lane >> 2;
    const int tg = lane & 3;
    const int wmBase = (warp & 7) * 32;          // 0..224
    const int wnBase = (warp >> 3) * 64;         // 0 or 64

    const int py = blockIdx.x;                   // 0..23
    const int rowBase = blockIdx.y * 256;        // 0..3840
    const int proj = py >> 3;
    const int hp = py & 7;

    const __half* A = g_hx + (size_t)rowBase * Cn;
    const __half* B = g_hw + (size_t)(proj * Hn + hp * 2) * Dn * Cn;

    __half* outbase = (proj == 0 ? g_qh : (proj == 1 ? g_kh : g_vh));
    const int b  = rowBase >> 10;
    const int t0 = rowBase & (Tn - 1);

    const int ar = tid >> 1;                     // 0..255 (A row)
    const int ah = (tid & 1) * 32;
    const int br = tid >> 2;                     // 0..127 (B row)
    const int bh_ = (tid & 3) * 16;
    const int r16 = lane & 15;
    const int ch = (lane >> 4) * 8;

    auto stage_load = [&](int s, int k0) {
        __half* As = sm + s * QKV_STAGE_HALFS;
        __half* Bs = As + 256 * 72;
#pragma unroll
        for (int i = 0; i < 4; i++)
            cp16(smaddr(&As[ar * 72 + ah + i * 8]), &A[(size_t)ar * Cn + k0 + ah + i * 8]);
#pragma unroll
        for (int i = 0; i < 2; i++)
            cp16(smaddr(&Bs[br * 72 + bh_ + i * 8]), &B[(size_t)br * Cn + k0 + bh_ + i * 8]);
        cp_commit();
    };

    float acc[2][8][4];
#pragma unroll
    for (int mt = 0; mt < 2; mt++)
#pragma unroll
        for (int j = 0; j < 8; j++)
#pragma unroll
            for (int e = 0; e < 4; e++) acc[mt][j][e] = 0.f;

    stage_load(0, 0);
    stage_load(1, 64);

    for (int i = 0; i < 16; i++) {
        const int cur = i % 3;
        if (i == 15) cp_wait0(); else cp_wait1();
        __syncthreads();
        if (i + 2 < 16) stage_load((i + 2) % 3, (i + 2) * 64);

        const __half* As = sm + cur * QKV_STAGE_HALFS;
        const __half* Bs = As + 256 * 72;

#pragma unroll
        for (int kk = 0; kk < 4; kk++) {
            const int kb = kk * 16;
            uint32_t af[2][4], bf0[8], bf1[8];
#pragma unroll
            for (int mt = 0; mt < 2; mt++)
                ldsm_x4(af[mt][0], af[mt][1], af[mt][2], af[mt][3],
                        smaddr(&As[(wmBase + mt * 16 + r16) * 72 + kb + ch]));
            ldsm_x4(bf0[0], bf0[1], bf0[2], bf0[3],
                    smaddr(&Bs[(wnBase + lane) * 72 + kb]));
            ldsm_x4(bf0[4], bf0[5], bf0[6], bf0[7],
                    smaddr(&Bs[(wnBase + 32 + lane) * 72 + kb]));
            ldsm_x4(bf1[0], bf1[1], bf1[2], bf1[3],
                    smaddr(&Bs[(wnBase + lane) * 72 + kb + 8]));
            ldsm_x4(bf1[4], bf1[5], bf1[6], bf1[7],
                    smaddr(&Bs[(wnBase + 32 + lane) * 72 + kb + 8]));
#pragma unroll
            for (int mt = 0; mt < 2; mt++)
#pragma unroll
                for (int j = 0; j < 8; j++)
                    mma_f16(acc[mt][j], af[mt][0], af[mt][1], af[mt][2], af[mt][3],
                            bf0[j], bf1[j]);
        }
    }

#pragma unroll
    for (int mt = 0; mt < 2; mt++) {
        int row0 = wmBase + mt * 16 + g;
#pragma unroll
        for (int j = 0; j < 8; j++) {
            int col = wnBase + j * 8 + tg * 2;
            int h = hp * 2 + (col >> 6);
            int d = col & 63;
            __half* ob = outbase + ((size_t)(b * Hn + h) * Tn + t0) * Dn + d;
            *(__half2*)&ob[(size_t)row0 * Dn] =
                __floats2half2_rn(acc[mt][j][0], acc[mt][j][1]);
            *(__half2*)&ob[(size_t)(row0 + 8) * Dn] =
                __floats2half2_rn(acc[mt][j][2], acc[mt][j][3]);
        }
    }
}

// ---------------------------------------------------------------------------
// Kernel 2: causal flash attention, fp16 mma + ldmatrix + cp.async 3-stage K/V.
// (unchanged from R11 passing kernel)
// ---------------------------------------------------------------------------
#define ATTN_KV_STAGE_HALFS (128 * 72)   // Ks 64*72 + Vs 64*72
#define ATTN_SMEM_HALFS (128 * 72 + 3 * ATTN_KV_STAGE_HALFS)

__global__ __launch_bounds__(256) void attn_fp16()
{
    extern __shared__ __align__(16) __half smh[];
    __half* Qs = smh;                        // [128][72] staging only
    __half* KV = smh + 128 * 72;             // 3 stages of (Ks,Vs)

    const int tid = threadIdx.x;
    const int lane = tid & 31;
    const int warp = tid >> 5;
    const int g = lane >> 2;
    const int tg = lane & 3;
    const int wm = warp * 16;
    const int qt = (int)gridDim.x - 1 - (int)blockIdx.x;
    const int bh = blockIdx.y;

    const int r16 = lane & 15;
    const int ch = (lane >> 4) * 8;

    uint32_t qf[4][4];
    {
        const __half* qb = g_qh + ((size_t)bh * Tn + (size_t)qt * 128) * Dn;
        int r = tid >> 1;
        int hs = (tid & 1) * 32;
#pragma unroll
        for (int i = 0; i < 4; i++)
            *(uint4*)&Qs[r * 72 + hs + i * 8] =
                *(const uint4*)&qb[(size_t)r * Dn + hs + i * 8];
        __syncwarp();
#pragma unroll
        for (int kk = 0; kk < 4; kk++)
            ldsm_x4(qf[kk][0], qf[kk][1], qf[kk][2], qf[kk][3],
                    smaddr(&Qs[(wm + r16) * 72 + kk * 16 + ch]));
    }

    float m0 = -CUDART_INF_F, m1 = -CUDART_INF_F;
    float l0 = 0.f, l1 = 0.f;
    float oacc[8][4];
#pragma unroll
    for (int j = 0; j < 8; j++)
#pragma unroll
        for (int e = 0; e < 4; e++) oacc[j][e] = 0.f;

    const int row0 = qt * 128 + wm + g;
    const int row1 = row0 + 8;
    const int rowWarpMax = qt * 128 + wm + 15;

    const __half* kbase = g_kh + (size_t)bh * Tn * Dn;
    const __half* vbase = g_vh + (size_t)bh * Tn * Dn;
    const int sr = tid >> 2;
    const int sh = (tid & 3) * 16;

    auto kv_load = [&](int s, int st) {
        __half* Ks = KV + s * ATTN_KV_STAGE_HALFS;
        __half* Vs = Ks + 64 * 72;
        const __half* kn = kbase + (size_t)st * 64 * Dn;
        const __half* vn = vbase + (size_t)st * 64 * Dn;
#pragma unroll
        for (int i = 0; i < 2; i++) {
            cp16(smaddr(&Ks[sr * 72 + sh + i * 8]), &kn[(size_t)sr * Dn + sh + i * 8]);
            cp16(smaddr(&Vs[sr * 72 + sh + i * 8]), &vn[(size_t)sr * Dn + sh + i * 8]);
        }
        cp_commit();
    };

    const int nst = 2 * qt + 2;
    kv_load(0, 0);
    if (nst > 1) kv_load(1, 1);

    for (int st = 0; st < nst; st++) {
        if (st == nst - 1) cp_wait0(); else cp_wait1();
        __syncthreads();
        if (st + 2 < nst) kv_load((st + 2) % 3, st + 2);

        if (st * 64 <= rowWarpMax) {
            const __half* Ks = KV + (st % 3) * ATTN_KV_STAGE_HALFS;
            const __half* Vs = Ks + 64 * 72;

            float c[8][4];
#pragma unroll
            for (int j = 0; j < 8; j++)
#pragma unroll
                for (int e = 0; e < 4; e++) c[j][e] = 0.f;

#pragma unroll
            for (int kk = 0; kk < 4; kk++) {
                const int kb = kk * 16;
                uint32_t b0lo[4], b0hi[4], b1lo[4], b1hi[4];
                ldsm_x4(b0lo[0], b0lo[1], b0lo[2], b0lo[3],
                        smaddr(&Ks[lane * 72 + kb]));
                ldsm_x4(b0hi[0], b0hi[1], b0hi[2], b0hi[3],
                        smaddr(&Ks[(32 + lane) * 72 + kb]));
                ldsm_x4(b1lo[0], b1lo[1], b1lo[2], b1lo[3],
                        smaddr(&Ks[lane * 72 + kb + 8]));
                ldsm_x4(b1hi[0], b1hi[1], b1hi[2], b1hi[3],
                        smaddr(&Ks[(32 + lane) * 72 + kb + 8]));
#pragma unroll
                for (int j = 0; j < 4; j++) {
                    mma_f16(c[j], qf[kk][0], qf[kk][1], qf[kk][2], qf[kk][3],
                            b0lo[j], b1lo[j]);
                    mma_f16(c[j + 4], qf[kk][0], qf[kk][1], qf[kk][2], qf[kk][3],
                            b0hi[j], b1hi[j]);
                }
            }

            const float scale = 0.125f;
            const bool maskt = (st * 64 + 63 > qt * 128);
#pragma unroll
            for (int j = 0; j < 8; j++) {
                int col = st * 64 + j * 8 + tg * 2;
                if (maskt) {
                    c[j][0] = (col     > row0) ? -CUDART_INF_F : c[j][0] * scale;
                    c[j][1] = (col + 1 > row0) ? -CUDART_INF_F : c[j][1] * scale;
                    c[j][2] = (col     > row1) ? -CUDART_INF_F : c[j][2] * scale;
                    c[j][3] = (col + 1 > row1) ? -CUDART_INF_F : c[j][3] * scale;
                } else {
                    c[j][0] *= scale; c[j][1] *= scale;
                    c[j][2] *= scale; c[j][3] *= scale;
                }
            }

            float t0 = -CUDART_INF_F, t1 = -CUDART_INF_F;
#pragma unroll
            for (int j = 0; j < 8; j++) {
                t0 = fmaxf(t0, fmaxf(c[j][0], c[j][1]));
                t1 = fmaxf(t1, fmaxf(c[j][2], c[j][3]));
            }
            t0 = fmaxf(t0, __shfl_xor_sync(0xffffffffu, t0, 1));
            t0 = fmaxf(t0, __shfl_xor_sync(0xffffffffu, t0, 2));
            t1 = fmaxf(t1, __shfl_xor_sync(0xffffffffu, t1, 1));
            t1 = fmaxf(t1, __shfl_xor_sync(0xffffffffu, t1, 2));

            float nm0 = fmaxf(m0, t0), nm1 = fmaxf(m1, t1);
            float al0 = __expf(m0 - nm0), al1 = __expf(m1 - nm1);
            float s0 = 0.f, s1 = 0.f;
#pragma unroll
            for (int j = 0; j < 8; j++) {
                c[j][0] = __expf(c[j][0] - nm0);
                c[j][1] = __expf(c[j][1] - nm0);
                c[j][2] = __expf(c[j][2] - nm1);
                c[j][3] = __expf(c[j][3] - nm1);
                s0 += c[j][0] + c[j][1];
                s1 += c[j][2] + c[j][3];
            }
            s0 += __shfl_xor_sync(0xffffffffu, s0, 1);
            s0 += __shfl_xor_sync(0xffffffffu, s0, 2);
            s1 += __shfl_xor_sync(0xffffffffu, s1, 1);
            s1 += __shfl_xor_sync(0xffffffffu, s1, 2);

            l0 = l0 * al0 + s0;  m0 = nm0;
            l1 = l1 * al1 + s1;  m1 = nm1;

#pragma unroll
            for (int j = 0; j < 8; j++) {
                oacc[j][0] *= al0; oacc[j][1] *= al0;
                oacc[j][2] *= al1; oacc[j][3] *= al1;
            }

#pragma unroll
            for (int kk = 0; kk < 4; kk++) {
                const int kb = kk * 16;
                uint32_t a0 = packh2(c[2 * kk][0], c[2 * kk][1]);
                uint32_t a1 = packh2(c[2 * kk][2], c[2 * kk][3]);
                uint32_t a2 = packh2(c[2 * kk + 1][0], c[2 * kk + 1][1]);
                uint32_t a3 = packh2(c[2 * kk + 1][2], c[2 * kk + 1][3]);

                uint32_t v0lo[4], v0hi[4], v1lo[4], v1hi[4];
                const int srow = lane & 7;
                const int dcol = (lane >> 3) * 8;
                ldsm_x4_trans(v0lo[0], v0lo[1], v0lo[2], v0lo[3],
                              smaddr(&Vs[(kb + srow) * 72 + dcol]));
                ldsm_x4_trans(v0hi[0], v0hi[1], v0hi[2], v0hi[3],
                              smaddr(&Vs[(kb + srow) * 72 + dcol + 32]));
                ldsm_x4_trans(v1lo[0], v1lo[1], v1lo[2], v1lo[3],
                              smaddr(&Vs[(kb + 8 + srow) * 72 + dcol]));
                ldsm_x4_trans(v1hi[0], v1hi[1], v1hi[2], v1hi[3],
                              smaddr(&Vs[(kb + 8 + srow) * 72 + dcol + 32]));
#pragma unroll
                for (int j = 0; j < 4; j++) {
                    mma_f16(oacc[j], a0, a1, a2, a3, v0lo[j], v1lo[j]);
                    mma_f16(oacc[j + 4], a0, a1, a2, a3, v0hi[j], v1hi[j]);
                }
            }
        }
    }

    const int b = bh >> 4, h = bh & 15;
    __half* ob = g_atth + ((size_t)b * Tn + (size_t)qt * 128) * (Hn * Dn) + h * Dn;
    float inv0 = 1.f / l0, inv1 = 1.f / l1;
#pragma unroll
    for (int j = 0; j < 8; j++) {
        int col = j * 8 + tg * 2;
        *(__half2*)&ob[(size_t)(wm + g) * (Hn * Dn) + col] =
            __floats2half2_rn(oacc[j][0] * inv0, oacc[j][1] * inv0);
        *(__half2*)&ob[(size_t)(wm + g + 8) * (Hn * Dn) + col] =
            __floats2half2_rn(oacc[j][2] * inv1, oacc[j][3] * inv1);
    }
}

// ---------------------------------------------------------------------------
// Kernel 3: output projection, fp16 mma + ldmatrix + cp.async 3-stage.
// (unchanged from R11 passing kernel)
// ---------------------------------------------------------------------------
#define GEMM_STAGE_HALFS (256 * 72)              // As 128*72 + Bs 128*72
#define GEMM_SMEM_BYTES (3 * GEMM_STAGE_HALFS * 2)   // 110592 B

__global__ __launch_bounds__(256, 2) void proj_fp16(
    const float* __restrict__ bp, float* __restrict__ out)
{
    extern __shared__ __align__(16) __half sm[];

    const int tid = threadIdx.x;
    const int lane = tid & 31;
    const int warp = tid >> 5;
    const int g = lane >> 2;
    const int tg = lane & 3;
    const int wmBase = (warp & 3) * 32;
    const int wnBase = (warp >> 2) * 64;

    const int n0 = blockIdx.x * 128;
    const int rowBase = blockIdx.y * 128;

    const __half* A = g_atth + (size_t)rowBase * Cn;
    const __half* B = g_hwpt + (size_t)n0 * Cn;
    float* O = out + (size_t)rowBase * Cn + n0;

    const int ar = tid >> 1;
    const int ah = (tid & 1) * 32;
    const int r16 = lane & 15;
    const int ch = (lane >> 4) * 8;

    auto stage_load = [&](int s, int k0) {
        __half* As = sm + s * GEMM_STAGE_HALFS;
        __half* Bs = As + 128 * 72;
#pragma unroll
        for (int i = 0; i < 4; i++) {
            cp16(smaddr(&As[ar * 72 + ah + i * 8]), &A[(size_t)ar * Cn + k0 + ah + i * 8]);
            cp16(smaddr(&Bs[ar * 72 + ah + i * 8]), &B[(size_t)ar * Cn + k0 + ah + i * 8]);
        }
        cp_commit();
    };

    float acc[2][8][4];
#pragma unroll
    for (int mt = 0; mt < 2; mt++)
#pragma unroll
        for (int j = 0; j < 8; j++)
#pragma unroll
            for (int e = 0; e < 4; e++) acc[mt][j][e] = 0.f;

    stage_load(0, 0);
    stage_load(1, 64);

    for (int i = 0; i < 16; i++) {
        const int cur = i % 3;
        if (i == 15) cp_wait0(); else cp_wait1();
        __syncthreads();
        if (i + 2 < 16) stage_load((i + 2) % 3, (i + 2) * 64);

        const __half* As = sm + cur * GEMM_STAGE_HALFS;
        const __half* Bs = As + 128 * 72;

#pragma unroll
        for (int kk = 0; kk < 4; kk++) {
            const int kb = kk * 16;
            uint32_t af[2][4], bf0[8], bf1[8];
#pragma unroll
            for (int mt = 0; mt < 2; mt++)
                ldsm_x4(af[mt][0], af[mt][1], af[mt][2], af[mt][3],
                        smaddr(&As[(wmBase + mt * 16 + r16) * 72 + kb + ch]));
            ldsm_x4(bf0[0], bf0[1], bf0[2], bf0[3],
                    smaddr(&Bs[(wnBase + lane) * 72 + kb]));
            ldsm_x4(bf0[4], bf0[5], bf0[6], bf0[7],
                    smaddr(&Bs[(wnBase + 32 + lane) * 72 + kb]));
            ldsm_x4(bf1[0], bf1[1], bf1[2], bf1[3],
                    smaddr(&Bs[(wnBase + lane) * 72 + kb + 8]));
            ldsm_x4(bf1[4], bf1[5], bf1[6], bf1[7],
                    smaddr(&Bs[(wnBase + 32 + lane) * 72 + kb + 8]));
#pragma unroll
            for (int mt = 0; mt < 2; mt++)
#pragma unroll
                for (int j = 0; j < 8; j++)
                    mma_f16(acc[mt][j], af[mt][0], af[mt][1], af[mt][2], af[mt][3],
                            bf0[j], bf1[j]);
        }
    }

#pragma unroll
    for (int mt = 0; mt < 2; mt++) {
        int row0 = wmBase + mt * 16 + g;
#pragma unroll
        for (int j = 0; j < 8; j++) {
            int col = wnBase + j * 8 + tg * 2;
            float b0 = bp[n0 + col];
            float b1 = bp[n0 + col + 1];
            *(float2*)&O[(size_t)row0 * Cn + col] =
                make_float2(acc[mt][j][0] + b0, acc[mt][j][1] + b1);
            *(float2*)&O[(size_t)(row0 + 8) * Cn + col] =
                make_float2(acc[mt][j][2] + b0, acc[mt][j][3] + b1);
        }
    }
}

// ---------------------------------------------------------------------------

extern "C" void kernel_launch(void* const* d_in, const int* in_sizes, int n_in,
                              void* d_out, int out_size)
{
    (void)in_sizes; (void)n_in; (void)out_size;
    const float* x  = (const float*)d_in[0];
    const float* Wq = (const float*)d_in[1];
    const float* Wk = (const float*)d_in[2];
    const float* Wv = (const float*)d_in[3];
    const float* Wp = (const float*)d_in[4];
    const float* bp = (const float*)d_in[5];
    float* out = (float*)d_out;

    __half* hwpt = nullptr;
    cudaGetSymbolAddress((void**)&hwpt, g_hwpt);

    const size_t attn_smem = ATTN_SMEM_HALFS * sizeof(__half);   // 73728 B
    cudaFuncSetAttribute(attn_fp16,
                         cudaFuncAttributeMaxDynamicSharedMemorySize,
                         (int)attn_smem);
    cudaFuncSetAttribute(qkv_fp16,
                         cudaFuncAttributeMaxDynamicSharedMemorySize,
                         QKV_SMEM_BYTES);                         // 165888 B
    cudaFuncSetAttribute(proj_fp16,
                         cudaFuncAttributeMaxDynamicSharedMemorySize,
                         GEMM_SMEM_BYTES);                        // 110592 B

    conv_x_kernel<<<Bn * Tn * Cn / (256 * 4), 256>>>(x);
    transcvt_w3<<<dim3(2, 32, 48), 256>>>(Wq, Wk, Wv);
    transcvt_kernel<<<dim3(32, 32, 1), 256>>>(Wp, hwpt, Cn, Cn);

    qkv_fp16<<<dim3(24, 16), 512, QKV_SMEM_BYTES>>>();
    attn_fp16<<<dim3(Tn / 128, Bn * Hn), 256, attn_smem>>>();
    proj_fp16<<<dim3(8, 32), 256, GEMM_SMEM_BYTES>>>(bp, out);
}